// round 2
// baseline (speedup 1.0000x reference)
#include <cuda_runtime.h>
#include <math.h>

#define GN 100000
#define GE 1600000
#define GF 500
#define GH1 8
#define GHC 64            // 8 heads * 8 ch
#define GC2 7
#define NEG 0.2f
#define NCHUNK 391        // ceil(GN/256)

// ---------------- scratch (static device globals; no allocation) ----------------
__device__ int   g_deg[GN];
__device__ int   g_off[GN + 1];
__device__ int   g_cursor[GN];
__device__ int   g_csr[GE];
__device__ int   g_part[NCHUNK];
__device__ float g_h1[GN * GHC];        // layer1 transformed features
__device__ float g_as1[GN * GH1];
__device__ float g_ad1[GN * GH1];
__device__ float g_hpost[GN * GHC];     // after agg + bias + relu + dropout mask
__device__ float g_z[GN * 8];           // layer2 transformed (7 used, padded to 8)
__device__ float g_as2[GN];
__device__ float g_ad2[GN];
__device__ float g_calib[NCHUNK];

__device__ __forceinline__ float lrelu(float v) { return v > 0.f ? v : NEG * v; }

// ---------------- CSR build ----------------
__global__ void k_zero_deg() {
    int i = blockIdx.x * blockDim.x + threadIdx.x;
    if (i < GN) g_deg[i] = 0;
}

__global__ void k_hist(const int* __restrict__ ei) {
    int e = blockIdx.x * blockDim.x + threadIdx.x;
    if (e < GE) atomicAdd(&g_deg[ei[GE + e]], 1);
}

__global__ void k_scan_block() {
    __shared__ int sh[256];
    int i = blockIdx.x * 256 + threadIdx.x;
    int v = (i < GN) ? g_deg[i] : 0;
    sh[threadIdx.x] = v;
    __syncthreads();
    // Hillis-Steele inclusive scan
    for (int d = 1; d < 256; d <<= 1) {
        int t = (threadIdx.x >= d) ? sh[threadIdx.x - d] : 0;
        __syncthreads();
        sh[threadIdx.x] += t;
        __syncthreads();
    }
    if (i < GN) g_off[i] = sh[threadIdx.x] - v;     // chunk-local exclusive
    if (threadIdx.x == 255) g_part[blockIdx.x] = sh[255];
}

__global__ void k_scan_part() {
    if (threadIdx.x == 0 && blockIdx.x == 0) {
        int run = 0;
        for (int b = 0; b < NCHUNK; b++) {
            int t = g_part[b];
            g_part[b] = run;
            run += t;
        }
        g_off[GN] = run;   // == GE
    }
}

__global__ void k_scan_add() {
    int i = blockIdx.x * 256 + threadIdx.x;
    if (i < GN) {
        int o = g_off[i] + g_part[blockIdx.x];
        g_off[i] = o;
        g_cursor[i] = o;
    }
}

__global__ void k_scatter(const int* __restrict__ ei) {
    int e = blockIdx.x * blockDim.x + threadIdx.x;
    if (e < GE) {
        int dst = ei[GE + e];
        int pos = atomicAdd(&g_cursor[dst], 1);
        g_csr[pos] = ei[e];
    }
}

// ---------------- GEMM1: h1 = x @ W1  (100000x500 @ 500x64) ----------------
// 64x64 tile per 256-thread block, 4x4 register blocking, K-tiles of 50.
__global__ __launch_bounds__(256) void k_gemm1(const float* __restrict__ x,
                                               const float* __restrict__ W) {
    __shared__ float sx[64][51];
    __shared__ float sw[50][64];
    int brow = blockIdx.x * 64;
    int tid = threadIdx.x;
    int tcol = tid & 15, trow = tid >> 4;
    float acc[4][4] = {};
    for (int k0 = 0; k0 < GF; k0 += 50) {
        for (int idx = tid; idx < 64 * 50; idx += 256) {
            int r = idx / 50, kk = idx % 50;
            int row = brow + r;
            sx[r][kk] = (row < GN) ? x[row * GF + k0 + kk] : 0.f;
        }
        for (int idx = tid; idx < 50 * 64; idx += 256) {
            int kk = idx >> 6, c = idx & 63;
            sw[kk][c] = W[(k0 + kk) * GHC + c];
        }
        __syncthreads();
#pragma unroll 10
        for (int kk = 0; kk < 50; kk++) {
            float a0 = sx[trow * 4 + 0][kk];
            float a1 = sx[trow * 4 + 1][kk];
            float a2 = sx[trow * 4 + 2][kk];
            float a3 = sx[trow * 4 + 3][kk];
            float4 b = *(const float4*)&sw[kk][tcol * 4];
            acc[0][0] += a0 * b.x; acc[0][1] += a0 * b.y; acc[0][2] += a0 * b.z; acc[0][3] += a0 * b.w;
            acc[1][0] += a1 * b.x; acc[1][1] += a1 * b.y; acc[1][2] += a1 * b.z; acc[1][3] += a1 * b.w;
            acc[2][0] += a2 * b.x; acc[2][1] += a2 * b.y; acc[2][2] += a2 * b.z; acc[2][3] += a2 * b.w;
            acc[3][0] += a3 * b.x; acc[3][1] += a3 * b.y; acc[3][2] += a3 * b.z; acc[3][3] += a3 * b.w;
        }
        __syncthreads();
    }
#pragma unroll
    for (int i = 0; i < 4; i++) {
        int row = brow + trow * 4 + i;
        if (row < GN) {
            float4 v = make_float4(acc[i][0], acc[i][1], acc[i][2], acc[i][3]);
            *(float4*)&g_h1[row * GHC + tcol * 4] = v;
        }
    }
}

// ---------------- alphas for layer 1 ----------------
__global__ void k_alphas1(const float* __restrict__ att_s, const float* __restrict__ att_d) {
    int gid = blockIdx.x * blockDim.x + threadIdx.x;
    if (gid >= GN * GH1) return;
    int h = gid & 7;
    const float* hp = g_h1 + (gid >> 3) * GHC + h * 8;
    float4 v0 = *(const float4*)hp;
    float4 v1 = *(const float4*)(hp + 4);
    const float* as = att_s + h * 8;
    const float* ad = att_d + h * 8;
    float s = v0.x * as[0] + v0.y * as[1] + v0.z * as[2] + v0.w * as[3]
            + v1.x * as[4] + v1.y * as[5] + v1.z * as[6] + v1.w * as[7];
    float d = v0.x * ad[0] + v0.y * ad[1] + v0.z * ad[2] + v0.w * ad[3]
            + v1.x * ad[4] + v1.y * ad[5] + v1.z * ad[6] + v1.w * ad[7];
    g_as1[gid] = s;
    g_ad1[gid] = d;
}

// ---------------- layer-1 aggregation (online segment softmax) ----------------
// thread = (node, head). Self loop processed first, then CSR in-edges.
__global__ void k_agg1(const float* __restrict__ b1, const float* __restrict__ mask) {
    int gid = blockIdx.x * blockDim.x + threadIdx.x;
    if (gid >= GN * GH1) return;
    int node = gid >> 3, h = gid & 7;
    float adst = g_ad1[gid];
    float m = lrelu(g_as1[gid] + adst);     // self edge
    float s = 1.0f;
    const float4* selfp = (const float4*)(g_h1 + node * GHC + h * 8);
    float4 a0 = selfp[0], a1 = selfp[1];
    int beg = g_off[node], end = g_off[node + 1];
    for (int i = beg; i < end; i++) {
        int src = g_csr[i];
        float ee = lrelu(__ldg(&g_as1[src * GH1 + h]) + adst);
        const float4* hp = (const float4*)(g_h1 + src * GHC + h * 8);
        float4 v0 = __ldg(hp), v1 = __ldg(hp + 1);
        float mn = fmaxf(m, ee);
        float sc = __expf(m - mn);
        float w  = __expf(ee - mn);
        s = s * sc + w;
        a0.x = a0.x * sc + w * v0.x; a0.y = a0.y * sc + w * v0.y;
        a0.z = a0.z * sc + w * v0.z; a0.w = a0.w * sc + w * v0.w;
        a1.x = a1.x * sc + w * v1.x; a1.y = a1.y * sc + w * v1.y;
        a1.z = a1.z * sc + w * v1.z; a1.w = a1.w * sc + w * v1.w;
        m = mn;
    }
    float inv = 1.0f / (s + 1e-16f);
    int base = node * GHC + h * 8;
    float out[8] = {a0.x, a0.y, a0.z, a0.w, a1.x, a1.y, a1.z, a1.w};
#pragma unroll
    for (int c = 0; c < 8; c++) {
        float v = out[c] * inv + b1[h * 8 + c];
        v = fmaxf(v, 0.f) * mask[base + c];
        g_hpost[base + c] = v;
    }
}

// ---------------- GEMM2 + alphas2: z = hpost @ W2 (64->7) ----------------
__global__ __launch_bounds__(256) void k_gemm2(const float* __restrict__ W2,
                                               const float* __restrict__ att_s,
                                               const float* __restrict__ att_d) {
    __shared__ float sw[64 * 7];
    __shared__ float sas[7], sad[7];
    for (int i = threadIdx.x; i < 64 * 7; i += blockDim.x) sw[i] = W2[i];   // FIX: strided load (448 > 256 threads)
    if (threadIdx.x < 7) { sas[threadIdx.x] = att_s[threadIdx.x]; sad[threadIdx.x] = att_d[threadIdx.x]; }
    __syncthreads();
    int node = blockIdx.x * blockDim.x + threadIdx.x;
    if (node >= GN) return;
    float zz[7] = {};
    const float* hr = g_hpost + node * GHC;
#pragma unroll 16
    for (int k = 0; k < 64; k++) {
        float hv = hr[k];
#pragma unroll
        for (int c = 0; c < 7; c++) zz[c] += hv * sw[k * 7 + c];
    }
    float as = 0.f, ad = 0.f;
#pragma unroll
    for (int c = 0; c < 7; c++) { as += zz[c] * sas[c]; ad += zz[c] * sad[c]; }
    float* zp = g_z + node * 8;
#pragma unroll
    for (int c = 0; c < 7; c++) zp[c] = zz[c];
    zp[7] = 0.f;
    g_as2[node] = as;
    g_ad2[node] = ad;
}

// ---------------- layer-2 aggregation + epilogue ----------------
__global__ __launch_bounds__(256) void k_agg2(const float* __restrict__ b2,
                                              float* __restrict__ out) {
    int node = blockIdx.x * blockDim.x + threadIdx.x;
    float calib = 0.f;
    if (node < GN) {
        float adst = g_ad2[node];
        float m = lrelu(g_as2[node] + adst);
        float s = 1.0f;
        const float4* zp = (const float4*)(g_z + node * 8);
        float4 a0 = zp[0], a1 = zp[1];
        int beg = g_off[node], end = g_off[node + 1];
        for (int i = beg; i < end; i++) {
            int src = g_csr[i];
            float ee = lrelu(__ldg(&g_as2[src]) + adst);
            const float4* vp = (const float4*)(g_z + src * 8);
            float4 v0 = __ldg(vp), v1 = __ldg(vp + 1);
            float mn = fmaxf(m, ee);
            float sc = __expf(m - mn);
            float w  = __expf(ee - mn);
            s = s * sc + w;
            a0.x = a0.x * sc + w * v0.x; a0.y = a0.y * sc + w * v0.y;
            a0.z = a0.z * sc + w * v0.z; a0.w = a0.w * sc + w * v0.w;
            a1.x = a1.x * sc + w * v1.x; a1.y = a1.y * sc + w * v1.y;
            a1.z = a1.z * sc + w * v1.z;
            m = mn;
        }
        float inv = 1.0f / (s + 1e-16f);
        float xo[7] = {a0.x, a0.y, a0.z, a0.w, a1.x, a1.y, a1.z};
#pragma unroll
        for (int c = 0; c < 7; c++) xo[c] = xo[c] * inv + b2[c];
        // softmax / log_softmax / top2 calibration
        float mx = xo[0];
#pragma unroll
        for (int c = 1; c < 7; c++) mx = fmaxf(mx, xo[c]);
        float ex[7], sum = 0.f;
#pragma unroll
        for (int c = 0; c < 7; c++) { ex[c] = expf(xo[c] - mx); sum += ex[c]; }
        float isum = 1.0f / sum;
        float lse = logf(sum);
        float p1 = -1.f, p2 = -1.f;
#pragma unroll
        for (int c = 0; c < 7; c++) {
            float p = ex[c] * isum;
            out[node * 7 + c] = xo[c] - mx - lse;           // log_softmax
            out[700001 + node * 7 + c] = p;                 // softmax
            if (p > p1) { p2 = p1; p1 = p; }
            else if (p > p2) { p2 = p; }
        }
        calib = 1.0f - p1 + p2;
    }
    // deterministic per-block reduction of calib
    __shared__ float red[256];
    red[threadIdx.x] = calib;
    __syncthreads();
    for (int d = 128; d > 0; d >>= 1) {
        if (threadIdx.x < d) red[threadIdx.x] += red[threadIdx.x + d];
        __syncthreads();
    }
    if (threadIdx.x == 0) g_calib[blockIdx.x] = red[0];
}

__global__ void k_final(float* __restrict__ out) {
    if (threadIdx.x == 0 && blockIdx.x == 0) {
        float s = 0.f;
        for (int b = 0; b < NCHUNK; b++) s += g_calib[b];
        out[700000] = s / (float)GN;
    }
}

// ---------------- launch ----------------
extern "C" void kernel_launch(void* const* d_in, const int* in_sizes, int n_in,
                              void* d_out, int out_size) {
    const float* x        = (const float*)d_in[0];
    const int*   ei       = (const int*)d_in[1];
    const float* mask     = (const float*)d_in[2];
    const float* W1       = (const float*)d_in[3];
    const float* att_s1   = (const float*)d_in[4];
    const float* att_d1   = (const float*)d_in[5];
    const float* b1       = (const float*)d_in[6];
    const float* W2       = (const float*)d_in[7];
    const float* att_s2   = (const float*)d_in[8];
    const float* att_d2   = (const float*)d_in[9];
    const float* b2       = (const float*)d_in[10];
    float* out = (float*)d_out;

    const int TB = 256;
    int eg = (GE + TB - 1) / TB;          // 6250
    int ng8 = (GN * GH1 + TB - 1) / TB;   // 3125

    // CSR build (reused by both layers)
    k_zero_deg<<<NCHUNK, TB>>>();
    k_hist<<<eg, TB>>>(ei);
    k_scan_block<<<NCHUNK, TB>>>();
    k_scan_part<<<1, 32>>>();
    k_scan_add<<<NCHUNK, TB>>>();
    k_scatter<<<eg, TB>>>(ei);

    // Layer 1
    k_gemm1<<<(GN + 63) / 64, TB>>>(x, W1);
    k_alphas1<<<ng8, TB>>>(att_s1, att_d1);
    k_agg1<<<ng8, TB>>>(b1, mask);

    // Layer 2
    k_gemm2<<<NCHUNK, TB>>>(W2, att_s2, att_d2);
    k_agg2<<<NCHUNK, TB>>>(b2, out);
    k_final<<<1, 32>>>(out);
}

// round 4
// speedup vs baseline: 1.4368x; 1.4368x over previous
#include <cuda_runtime.h>
#include <cuda_bf16.h>
#include <math.h>
#include <stdint.h>

#define GN 100000
#define GE 1600000
#define GF 500
#define GH1 8
#define GHC 64            // 8 heads * 8 ch
#define GC2 7
#define NEG 0.2f
#define NCHUNK 391        // ceil(GN/256)
#define GM1_GRID 782      // ceil(GN/128)

// ---------------- scratch (static device globals; no allocation) ----------------
__device__ int   g_deg[GN];
__device__ int   g_off[GN + 1];
__device__ int   g_cursor[GN];
__device__ int   g_csr[GE];
__device__ int   g_part[NCHUNK];
__device__ float g_h1[GN * GHC];
__device__ float g_as1[GN * GH1];
__device__ float g_ad1[GN * GH1];
__device__ float g_hpost[GN * GHC];
__device__ float g_z[GN * 8];
__device__ float g_as2[GN];
__device__ float g_ad2[GN];
__device__ float g_calib[NCHUNK];

__device__ __forceinline__ float lrelu(float v) { return v > 0.f ? v : NEG * v; }

// ---------------- CSR build ----------------
__global__ void k_zero_deg() {
    int i = blockIdx.x * blockDim.x + threadIdx.x;
    if (i < GN) g_deg[i] = 0;
}

__global__ void k_hist(const int* __restrict__ ei) {
    int e = blockIdx.x * blockDim.x + threadIdx.x;
    if (e < GE) atomicAdd(&g_deg[ei[GE + e]], 1);
}

__global__ void k_scan_block() {
    __shared__ int sh[256];
    int i = blockIdx.x * 256 + threadIdx.x;
    int v = (i < GN) ? g_deg[i] : 0;
    sh[threadIdx.x] = v;
    __syncthreads();
    for (int d = 1; d < 256; d <<= 1) {
        int t = (threadIdx.x >= d) ? sh[threadIdx.x - d] : 0;
        __syncthreads();
        sh[threadIdx.x] += t;
        __syncthreads();
    }
    if (i < GN) g_off[i] = sh[threadIdx.x] - v;
    if (threadIdx.x == 255) g_part[blockIdx.x] = sh[255];
}

__global__ void k_scan_part() {
    __shared__ int sh[512];
    int i = threadIdx.x;
    int v = (i < NCHUNK) ? g_part[i] : 0;
    sh[i] = v;
    __syncthreads();
    for (int d = 1; d < 512; d <<= 1) {
        int t = (i >= d) ? sh[i - d] : 0;
        __syncthreads();
        sh[i] += t;
        __syncthreads();
    }
    if (i < NCHUNK) g_part[i] = sh[i] - v;      // exclusive
    if (i == 511) g_off[GN] = sh[511];          // == GE
}

__global__ void k_scan_add() {
    int i = blockIdx.x * 256 + threadIdx.x;
    if (i < GN) {
        int o = g_off[i] + g_part[blockIdx.x];
        g_off[i] = o;
        g_cursor[i] = o;
    }
}

__global__ void k_scatter(const int* __restrict__ ei) {
    int e = blockIdx.x * blockDim.x + threadIdx.x;
    if (e < GE) {
        int dst = ei[GE + e];
        int pos = atomicAdd(&g_cursor[dst], 1);
        g_csr[pos] = ei[e];
    }
}

// ---------------- GEMM1 via HMMA mma.sync (split-bf16) ----------------
// 128x64 output tile per CTA, 8 warps (4x2 grid, warp tile 32x32), K staged 8x64.
// A/B stored hi+lo bf16; D += Ahi*Bhi + Ahi*Blo + Alo*Bhi (fp32 accum).
#define SA 72                      // smem row stride in bf16 elems (36 words)
#define SAW 36
#define OFF_AHI 0
#define OFF_ALO (128 * SA * 2)              // 18432
#define OFF_BHI (2 * 128 * SA * 2)          // 36864
#define OFF_BLO (2 * 128 * SA * 2 + 64 * SA * 2)   // 46080
#define SMEM_SZ (2 * 128 * SA * 2 + 2 * 64 * SA * 2) // 55296

#define MMA_BF16(c, a, b) \
    asm volatile("mma.sync.aligned.m16n8k16.row.col.f32.bf16.bf16.f32 " \
        "{%0,%1,%2,%3}, {%4,%5,%6,%7}, {%8,%9}, {%0,%1,%2,%3};" \
        : "+f"((c)[0]), "+f"((c)[1]), "+f"((c)[2]), "+f"((c)[3]) \
        : "r"((a)[0]), "r"((a)[1]), "r"((a)[2]), "r"((a)[3]), "r"((b)[0]), "r"((b)[1]))

__global__ __launch_bounds__(256, 2) void k_gemm1_tc(const float* __restrict__ x,
                                                     const float* __restrict__ W) {
    extern __shared__ char smem[];
    uint32_t* A32h = (uint32_t*)(smem + OFF_AHI);
    uint32_t* A32l = (uint32_t*)(smem + OFF_ALO);
    uint32_t* B32h = (uint32_t*)(smem + OFF_BHI);
    uint32_t* B32l = (uint32_t*)(smem + OFF_BLO);

    int tid = threadIdx.x, wid = tid >> 5, lid = tid & 31;
    int wm = wid >> 1, wn = wid & 1;
    int g = lid >> 2, tg = lid & 3;
    int brow = blockIdx.x * 128;

    float acc[2][4][4] = {};

    for (int st = 0; st < 8; st++) {
        int k0 = st * 64;
        if (st) __syncthreads();
        // ---- A: x[brow..brow+128) x k0..k0+64 -> hi/lo bf16
        for (int slot = tid; slot < 2048; slot += 256) {
            int r = slot >> 4, f4 = slot & 15;
            int row = brow + r, k = k0 + f4 * 4;
            float4 v = make_float4(0.f, 0.f, 0.f, 0.f);
            if (row < GN && k < GF) v = *(const float4*)(x + (size_t)row * GF + k);
            __nv_bfloat16 hx = __float2bfloat16(v.x), hy = __float2bfloat16(v.y);
            __nv_bfloat16 hz = __float2bfloat16(v.z), hw = __float2bfloat16(v.w);
            __nv_bfloat16 lx = __float2bfloat16(v.x - __bfloat162float(hx));
            __nv_bfloat16 ly = __float2bfloat16(v.y - __bfloat162float(hy));
            __nv_bfloat16 lz = __float2bfloat16(v.z - __bfloat162float(hz));
            __nv_bfloat16 lw = __float2bfloat16(v.w - __bfloat162float(hw));
            __nv_bfloat162 h01 = {hx, hy}, h23 = {hz, hw};
            __nv_bfloat162 l01 = {lx, ly}, l23 = {lz, lw};
            int w0 = r * SAW + f4 * 2;
            A32h[w0]     = *(uint32_t*)&h01;
            A32h[w0 + 1] = *(uint32_t*)&h23;
            A32l[w0]     = *(uint32_t*)&l01;
            A32l[w0 + 1] = *(uint32_t*)&l23;
        }
        // ---- B: W[k0..k0+64) x 64 -> sB[n][kk] hi/lo
        for (int i = tid; i < 4096; i += 256) {
            int n = i & 63, kk = i >> 6;
            int k = k0 + kk;
            float w = (k < GF) ? W[(size_t)k * 64 + n] : 0.f;
            __nv_bfloat16 hw = __float2bfloat16(w);
            __nv_bfloat16 lw = __float2bfloat16(w - __bfloat162float(hw));
            *(__nv_bfloat16*)(smem + OFF_BHI + (n * SA + kk) * 2) = hw;
            *(__nv_bfloat16*)(smem + OFF_BLO + (n * SA + kk) * 2) = lw;
        }
        __syncthreads();

#pragma unroll
        for (int ks = 0; ks < 4; ks++) {
            int kw = ks * 8 + tg;
            uint32_t ah[2][4], al[2][4], bh[4][2], bl[4][2];
#pragma unroll
            for (int fm = 0; fm < 2; fm++) {
                int r0 = (wm * 32 + fm * 16 + g) * SAW;
                ah[fm][0] = A32h[r0 + kw];
                ah[fm][1] = A32h[r0 + 8 * SAW + kw];
                ah[fm][2] = A32h[r0 + kw + 4];
                ah[fm][3] = A32h[r0 + 8 * SAW + kw + 4];
                al[fm][0] = A32l[r0 + kw];
                al[fm][1] = A32l[r0 + 8 * SAW + kw];
                al[fm][2] = A32l[r0 + kw + 4];
                al[fm][3] = A32l[r0 + 8 * SAW + kw + 4];
            }
#pragma unroll
            for (int fn = 0; fn < 4; fn++) {
                int n0 = (wn * 32 + fn * 8 + g) * SAW;
                bh[fn][0] = B32h[n0 + kw];
                bh[fn][1] = B32h[n0 + kw + 4];
                bl[fn][0] = B32l[n0 + kw];
                bl[fn][1] = B32l[n0 + kw + 4];
            }
#pragma unroll
            for (int fm = 0; fm < 2; fm++)
#pragma unroll
                for (int fn = 0; fn < 4; fn++) {
                    MMA_BF16(acc[fm][fn], ah[fm], bh[fn]);
                    MMA_BF16(acc[fm][fn], ah[fm], bl[fn]);
                    MMA_BF16(acc[fm][fn], al[fm], bh[fn]);
                }
        }
    }

    // ---- epilogue: write h1
#pragma unroll
    for (int fm = 0; fm < 2; fm++) {
        int row = brow + wm * 32 + fm * 16 + g;
#pragma unroll
        for (int fn = 0; fn < 4; fn++) {
            int col = wn * 32 + fn * 8 + tg * 2;
            if (row < GN)
                *(float2*)&g_h1[(size_t)row * GHC + col] = make_float2(acc[fm][fn][0], acc[fm][fn][1]);
            if (row + 8 < GN)
                *(float2*)&g_h1[(size_t)(row + 8) * GHC + col] = make_float2(acc[fm][fn][2], acc[fm][fn][3]);
        }
    }
}

// ---------------- alphas for layer 1 ----------------
__global__ void k_alphas1(const float* __restrict__ att_s, const float* __restrict__ att_d) {
    int gid = blockIdx.x * blockDim.x + threadIdx.x;
    if (gid >= GN * GH1) return;
    int h = gid & 7;
    const float* hp = g_h1 + (size_t)(gid >> 3) * GHC + h * 8;
    float4 v0 = *(const float4*)hp;
    float4 v1 = *(const float4*)(hp + 4);
    const float* as = att_s + h * 8;
    const float* ad = att_d + h * 8;
    float s = v0.x * as[0] + v0.y * as[1] + v0.z * as[2] + v0.w * as[3]
            + v1.x * as[4] + v1.y * as[5] + v1.z * as[6] + v1.w * as[7];
    float d = v0.x * ad[0] + v0.y * ad[1] + v0.z * ad[2] + v0.w * ad[3]
            + v1.x * ad[4] + v1.y * ad[5] + v1.z * ad[6] + v1.w * ad[7];
    g_as1[gid] = s;
    g_ad1[gid] = d;
}

// ---------------- layer-1 aggregation (online segment softmax) ----------------
__global__ void k_agg1(const float* __restrict__ b1, const float* __restrict__ mask) {
    int gid = blockIdx.x * blockDim.x + threadIdx.x;
    if (gid >= GN * GH1) return;
    int node = gid >> 3, h = gid & 7;
    float adst = g_ad1[gid];
    float m = lrelu(g_as1[gid] + adst);     // self edge
    float s = 1.0f;
    const float4* selfp = (const float4*)(g_h1 + (size_t)node * GHC + h * 8);
    float4 a0 = selfp[0], a1 = selfp[1];
    int beg = g_off[node], end = g_off[node + 1];
    for (int i = beg; i < end; i++) {
        int src = g_csr[i];
        float ee = lrelu(__ldg(&g_as1[src * GH1 + h]) + adst);
        const float4* hp = (const float4*)(g_h1 + (size_t)src * GHC + h * 8);
        float4 v0 = __ldg(hp), v1 = __ldg(hp + 1);
        float mn = fmaxf(m, ee);
        float sc = __expf(m - mn);
        float w  = __expf(ee - mn);
        s = s * sc + w;
        a0.x = a0.x * sc + w * v0.x; a0.y = a0.y * sc + w * v0.y;
        a0.z = a0.z * sc + w * v0.z; a0.w = a0.w * sc + w * v0.w;
        a1.x = a1.x * sc + w * v1.x; a1.y = a1.y * sc + w * v1.y;
        a1.z = a1.z * sc + w * v1.z; a1.w = a1.w * sc + w * v1.w;
        m = mn;
    }
    float inv = 1.0f / (s + 1e-16f);
    int base = node * GHC + h * 8;
    float out[8] = {a0.x, a0.y, a0.z, a0.w, a1.x, a1.y, a1.z, a1.w};
#pragma unroll
    for (int c = 0; c < 8; c++) {
        float v = out[c] * inv + b1[h * 8 + c];
        v = fmaxf(v, 0.f) * mask[base + c];
        g_hpost[base + c] = v;
    }
}

// ---------------- GEMM2 + alphas2 ----------------
__global__ __launch_bounds__(256) void k_gemm2(const float* __restrict__ W2,
                                               const float* __restrict__ att_s,
                                               const float* __restrict__ att_d) {
    __shared__ float sw[64 * 7];
    __shared__ float sas[7], sad[7];
    for (int i = threadIdx.x; i < 64 * 7; i += blockDim.x) sw[i] = W2[i];
    if (threadIdx.x < 7) { sas[threadIdx.x] = att_s[threadIdx.x]; sad[threadIdx.x] = att_d[threadIdx.x]; }
    __syncthreads();
    int node = blockIdx.x * blockDim.x + threadIdx.x;
    if (node >= GN) return;
    float zz[7] = {};
    const float* hr = g_hpost + (size_t)node * GHC;
#pragma unroll 16
    for (int k = 0; k < 64; k++) {
        float hv = hr[k];
#pragma unroll
        for (int c = 0; c < 7; c++) zz[c] += hv * sw[k * 7 + c];
    }
    float as = 0.f, ad = 0.f;
#pragma unroll
    for (int c = 0; c < 7; c++) { as += zz[c] * sas[c]; ad += zz[c] * sad[c]; }
    float* zp = g_z + (size_t)node * 8;
#pragma unroll
    for (int c = 0; c < 7; c++) zp[c] = zz[c];
    zp[7] = 0.f;
    g_as2[node] = as;
    g_ad2[node] = ad;
}

// ---------------- layer-2 aggregation + epilogue ----------------
__global__ __launch_bounds__(256) void k_agg2(const float* __restrict__ b2,
                                              float* __restrict__ out) {
    int node = blockIdx.x * blockDim.x + threadIdx.x;
    float calib = 0.f;
    if (node < GN) {
        float adst = g_ad2[node];
        float m = lrelu(g_as2[node] + adst);
        float s = 1.0f;
        const float4* zp = (const float4*)(g_z + (size_t)node * 8);
        float4 a0 = zp[0], a1 = zp[1];
        int beg = g_off[node], end = g_off[node + 1];
        for (int i = beg; i < end; i++) {
            int src = g_csr[i];
            float ee = lrelu(__ldg(&g_as2[src]) + adst);
            const float4* vp = (const float4*)(g_z + (size_t)src * 8);
            float4 v0 = __ldg(vp), v1 = __ldg(vp + 1);
            float mn = fmaxf(m, ee);
            float sc = __expf(m - mn);
            float w  = __expf(ee - mn);
            s = s * sc + w;
            a0.x = a0.x * sc + w * v0.x; a0.y = a0.y * sc + w * v0.y;
            a0.z = a0.z * sc + w * v0.z; a0.w = a0.w * sc + w * v0.w;
            a1.x = a1.x * sc + w * v1.x; a1.y = a1.y * sc + w * v1.y;
            a1.z = a1.z * sc + w * v1.z;
            m = mn;
        }
        float inv = 1.0f / (s + 1e-16f);
        float xo[7] = {a0.x, a0.y, a0.z, a0.w, a1.x, a1.y, a1.z};
#pragma unroll
        for (int c = 0; c < 7; c++) xo[c] = xo[c] * inv + b2[c];
        float mx = xo[0];
#pragma unroll
        for (int c = 1; c < 7; c++) mx = fmaxf(mx, xo[c]);
        float ex[7], sum = 0.f;
#pragma unroll
        for (int c = 0; c < 7; c++) { ex[c] = expf(xo[c] - mx); sum += ex[c]; }
        float isum = 1.0f / sum;
        float lse = logf(sum);
        float p1 = -1.f, p2 = -1.f;
#pragma unroll
        for (int c = 0; c < 7; c++) {
            float p = ex[c] * isum;
            out[node * 7 + c] = xo[c] - mx - lse;           // log_softmax
            out[700001 + node * 7 + c] = p;                 // softmax
            if (p > p1) { p2 = p1; p1 = p; }
            else if (p > p2) { p2 = p; }
        }
        calib = 1.0f - p1 + p2;
    }
    __shared__ float red[256];
    red[threadIdx.x] = calib;
    __syncthreads();
    for (int d = 128; d > 0; d >>= 1) {
        if (threadIdx.x < d) red[threadIdx.x] += red[threadIdx.x + d];
        __syncthreads();
    }
    if (threadIdx.x == 0) g_calib[blockIdx.x] = red[0];
}

__global__ void k_final(float* __restrict__ out) {
    if (threadIdx.x == 0 && blockIdx.x == 0) {
        float s = 0.f;
        for (int b = 0; b < NCHUNK; b++) s += g_calib[b];
        out[700000] = s / (float)GN;
    }
}

// ---------------- launch ----------------
extern "C" void kernel_launch(void* const* d_in, const int* in_sizes, int n_in,
                              void* d_out, int out_size) {
    const float* x        = (const float*)d_in[0];
    const int*   ei       = (const int*)d_in[1];
    const float* mask     = (const float*)d_in[2];
    const float* W1       = (const float*)d_in[3];
    const float* att_s1   = (const float*)d_in[4];
    const float* att_d1   = (const float*)d_in[5];
    const float* b1       = (const float*)d_in[6];
    const float* W2       = (const float*)d_in[7];
    const float* att_s2   = (const float*)d_in[8];
    const float* att_d2   = (const float*)d_in[9];
    const float* b2       = (const float*)d_in[10];
    float* out = (float*)d_out;

    cudaFuncSetAttribute(k_gemm1_tc, cudaFuncAttributeMaxDynamicSharedMemorySize, SMEM_SZ);

    const int TB = 256;
    int eg = (GE + TB - 1) / TB;          // 6250
    int ng8 = (GN * GH1 + TB - 1) / TB;   // 3125

    // CSR build
    k_zero_deg<<<NCHUNK, TB>>>();
    k_hist<<<eg, TB>>>(ei);
    k_scan_block<<<NCHUNK, TB>>>();
    k_scan_part<<<1, 512>>>();
    k_scan_add<<<NCHUNK, TB>>>();
    k_scatter<<<eg, TB>>>(ei);

    // Layer 1
    k_gemm1_tc<<<GM1_GRID, TB, SMEM_SZ>>>(x, W1);
    k_alphas1<<<ng8, TB>>>(att_s1, att_d1);
    k_agg1<<<ng8, TB>>>(b1, mask);

    // Layer 2
    k_gemm2<<<NCHUNK, TB>>>(W2, att_s2, att_d2);
    k_agg2<<<NCHUNK, TB>>>(b2, out);
    k_final<<<1, 32>>>(out);
}

// round 5
// speedup vs baseline: 1.5830x; 1.1018x over previous
#include <cuda_runtime.h>
#include <cuda_bf16.h>
#include <math.h>
#include <stdint.h>

#define GN 100000
#define GE 1600000
#define GF 500
#define GH1 8
#define GHC 64
#define GC2 7
#define NEG 0.2f
#define NCHUNK 391        // ceil(GN/256)
#define NB8 3125          // GN*8/256 exact
#define GM1_GRID 782      // ceil(GN/128)

// ---------------- scratch ----------------
__device__ int   g_deg[GN];
__device__ int   g_off[GN + 1];
__device__ int   g_cursor[GN];
__device__ int   g_csr[GE];
__device__ int   g_part[NCHUNK];
__device__ float g_h1[GN * GHC];
__device__ float g_as1[GN * GH1];
__device__ float g_ad1[GN * GH1];
__device__ float g_z[GN * 8];
__device__ float g_as2[GN];
__device__ float g_ad2[GN];
__device__ float g_calib[NB8];

__device__ __forceinline__ float lrelu(float v) { return v > 0.f ? v : NEG * v; }

// ---------------- CSR build ----------------
__global__ void k_zero_deg() {
    int i = blockIdx.x * blockDim.x + threadIdx.x;
    if (i < GN) g_deg[i] = 0;
}

__global__ void k_hist(const int* __restrict__ ei) {
    int e = blockIdx.x * blockDim.x + threadIdx.x;
    if (e < GE) atomicAdd(&g_deg[ei[GE + e]], 1);
}

__global__ void k_scan_block() {
    __shared__ int sh[256];
    int i = blockIdx.x * 256 + threadIdx.x;
    int v = (i < GN) ? g_deg[i] : 0;
    sh[threadIdx.x] = v;
    __syncthreads();
    for (int d = 1; d < 256; d <<= 1) {
        int t = (threadIdx.x >= d) ? sh[threadIdx.x - d] : 0;
        __syncthreads();
        sh[threadIdx.x] += t;
        __syncthreads();
    }
    if (i < GN) g_off[i] = sh[threadIdx.x] - v;
    if (threadIdx.x == 255) g_part[blockIdx.x] = sh[255];
}

__global__ void k_scan_part() {
    __shared__ int sh[512];
    int i = threadIdx.x;
    int v = (i < NCHUNK) ? g_part[i] : 0;
    sh[i] = v;
    __syncthreads();
    for (int d = 1; d < 512; d <<= 1) {
        int t = (i >= d) ? sh[i - d] : 0;
        __syncthreads();
        sh[i] += t;
        __syncthreads();
    }
    if (i < NCHUNK) g_part[i] = sh[i] - v;
    if (i == 511) g_off[GN] = sh[511];
}

__global__ void k_scan_add() {
    int i = blockIdx.x * 256 + threadIdx.x;
    if (i < GN) {
        int o = g_off[i] + g_part[blockIdx.x];
        g_off[i] = o;
        g_cursor[i] = o;
    }
}

__global__ void k_scatter(const int* __restrict__ ei) {
    int e = blockIdx.x * blockDim.x + threadIdx.x;
    if (e < GE) {
        int dst = ei[GE + e];
        int pos = atomicAdd(&g_cursor[dst], 1);
        g_csr[pos] = ei[e];
    }
}

// ---------------- GEMM1 via HMMA (split-bf16) + fused alphas1 ----------------
#define SA 72
#define SAW 36
#define OFF_AHI 0
#define OFF_ALO (128 * SA * 2)
#define OFF_BHI (2 * 128 * SA * 2)
#define OFF_BLO (2 * 128 * SA * 2 + 64 * SA * 2)
#define SMEM_SZ (2 * 128 * SA * 2 + 2 * 64 * SA * 2)

#define MMA_BF16(c, a, b) \
    asm volatile("mma.sync.aligned.m16n8k16.row.col.f32.bf16.bf16.f32 " \
        "{%0,%1,%2,%3}, {%4,%5,%6,%7}, {%8,%9}, {%0,%1,%2,%3};" \
        : "+f"((c)[0]), "+f"((c)[1]), "+f"((c)[2]), "+f"((c)[3]) \
        : "r"((a)[0]), "r"((a)[1]), "r"((a)[2]), "r"((a)[3]), "r"((b)[0]), "r"((b)[1]))

__global__ __launch_bounds__(256, 2) void k_gemm1_tc(const float* __restrict__ x,
                                                     const float* __restrict__ W,
                                                     const float* __restrict__ att_s,
                                                     const float* __restrict__ att_d) {
    extern __shared__ char smem[];
    uint32_t* A32h = (uint32_t*)(smem + OFF_AHI);
    uint32_t* A32l = (uint32_t*)(smem + OFF_ALO);
    uint32_t* B32h = (uint32_t*)(smem + OFF_BHI);
    uint32_t* B32l = (uint32_t*)(smem + OFF_BLO);

    int tid = threadIdx.x, wid = tid >> 5, lid = tid & 31;
    int wm = wid >> 1, wn = wid & 1;
    int g = lid >> 2, tg = lid & 3;
    int brow = blockIdx.x * 128;

    float acc[2][4][4] = {};

    for (int st = 0; st < 8; st++) {
        int k0 = st * 64;
        if (st) __syncthreads();
        for (int slot = tid; slot < 2048; slot += 256) {
            int r = slot >> 4, f4 = slot & 15;
            int row = brow + r, k = k0 + f4 * 4;
            float4 v = make_float4(0.f, 0.f, 0.f, 0.f);
            if (row < GN && k < GF) v = *(const float4*)(x + (size_t)row * GF + k);
            __nv_bfloat16 hx = __float2bfloat16(v.x), hy = __float2bfloat16(v.y);
            __nv_bfloat16 hz = __float2bfloat16(v.z), hw = __float2bfloat16(v.w);
            __nv_bfloat16 lx = __float2bfloat16(v.x - __bfloat162float(hx));
            __nv_bfloat16 ly = __float2bfloat16(v.y - __bfloat162float(hy));
            __nv_bfloat16 lz = __float2bfloat16(v.z - __bfloat162float(hz));
            __nv_bfloat16 lw = __float2bfloat16(v.w - __bfloat162float(hw));
            __nv_bfloat162 h01 = {hx, hy}, h23 = {hz, hw};
            __nv_bfloat162 l01 = {lx, ly}, l23 = {lz, lw};
            int w0 = r * SAW + f4 * 2;
            A32h[w0]     = *(uint32_t*)&h01;
            A32h[w0 + 1] = *(uint32_t*)&h23;
            A32l[w0]     = *(uint32_t*)&l01;
            A32l[w0 + 1] = *(uint32_t*)&l23;
        }
        for (int i = tid; i < 4096; i += 256) {
            int n = i & 63, kk = i >> 6;
            int k = k0 + kk;
            float w = (k < GF) ? W[(size_t)k * 64 + n] : 0.f;
            __nv_bfloat16 hw = __float2bfloat16(w);
            __nv_bfloat16 lw = __float2bfloat16(w - __bfloat162float(hw));
            *(__nv_bfloat16*)(smem + OFF_BHI + (n * SA + kk) * 2) = hw;
            *(__nv_bfloat16*)(smem + OFF_BLO + (n * SA + kk) * 2) = lw;
        }
        __syncthreads();

#pragma unroll
        for (int ks = 0; ks < 4; ks++) {
            int kw = ks * 8 + tg;
            uint32_t ah[2][4], al[2][4], bh[4][2], bl[4][2];
#pragma unroll
            for (int fm = 0; fm < 2; fm++) {
                int r0 = (wm * 32 + fm * 16 + g) * SAW;
                ah[fm][0] = A32h[r0 + kw];
                ah[fm][1] = A32h[r0 + 8 * SAW + kw];
                ah[fm][2] = A32h[r0 + kw + 4];
                ah[fm][3] = A32h[r0 + 8 * SAW + kw + 4];
                al[fm][0] = A32l[r0 + kw];
                al[fm][1] = A32l[r0 + 8 * SAW + kw];
                al[fm][2] = A32l[r0 + kw + 4];
                al[fm][3] = A32l[r0 + 8 * SAW + kw + 4];
            }
#pragma unroll
            for (int fn = 0; fn < 4; fn++) {
                int n0 = (wn * 32 + fn * 8 + g) * SAW;
                bh[fn][0] = B32h[n0 + kw];
                bh[fn][1] = B32h[n0 + kw + 4];
                bl[fn][0] = B32l[n0 + kw];
                bl[fn][1] = B32l[n0 + kw + 4];
            }
#pragma unroll
            for (int fm = 0; fm < 2; fm++)
#pragma unroll
                for (int fn = 0; fn < 4; fn++) {
                    MMA_BF16(acc[fm][fn], ah[fm], bh[fn]);
                    MMA_BF16(acc[fm][fn], ah[fm], bl[fn]);
                    MMA_BF16(acc[fm][fn], al[fm], bh[fn]);
                }
        }
    }

    // ---- epilogue: write h1 + fused as1/ad1
    float as_c[4][2], ad_c[4][2];
#pragma unroll
    for (int fn = 0; fn < 4; fn++) {
        int col = wn * 32 + fn * 8 + tg * 2;
        as_c[fn][0] = __ldg(&att_s[col]);     as_c[fn][1] = __ldg(&att_s[col + 1]);
        ad_c[fn][0] = __ldg(&att_d[col]);     ad_c[fn][1] = __ldg(&att_d[col + 1]);
    }
#pragma unroll
    for (int fm = 0; fm < 2; fm++) {
#pragma unroll
        for (int half = 0; half < 2; half++) {
            int row = brow + wm * 32 + fm * 16 + g + half * 8;
            float sh[4], dh[4];
#pragma unroll
            for (int fn = 0; fn < 4; fn++) {
                int col = wn * 32 + fn * 8 + tg * 2;
                float c0 = acc[fm][fn][2 * half], c1 = acc[fm][fn][2 * half + 1];
                if (row < GN)
                    *(float2*)&g_h1[(size_t)row * GHC + col] = make_float2(c0, c1);
                sh[fn] = c0 * as_c[fn][0] + c1 * as_c[fn][1];
                dh[fn] = c0 * ad_c[fn][0] + c1 * ad_c[fn][1];
            }
#pragma unroll
            for (int w = 1; w < 4; w <<= 1)
#pragma unroll
                for (int fn = 0; fn < 4; fn++) {
                    sh[fn] += __shfl_xor_sync(0xffffffffu, sh[fn], w, 4);
                    dh[fn] += __shfl_xor_sync(0xffffffffu, dh[fn], w, 4);
                }
            if (tg == 0 && row < GN) {
#pragma unroll
                for (int fn = 0; fn < 4; fn++) {
                    g_as1[row * 8 + wn * 4 + fn] = sh[fn];
                    g_ad1[row * 8 + wn * 4 + fn] = dh[fn];
                }
            }
        }
    }
}

// ---------------- layer-1 agg (no-max softmax) + fused GEMM2/alphas2 ----------------
__global__ __launch_bounds__(256) void k_agg1(const float* __restrict__ b1,
                                              const float* __restrict__ mask,
                                              const float* __restrict__ W2,
                                              const float* __restrict__ as2v,
                                              const float* __restrict__ ad2v) {
    __shared__ float sw[448], sas[7], sad[7];
    for (int i = threadIdx.x; i < 448; i += 256) sw[i] = W2[i];
    if (threadIdx.x < 7) { sas[threadIdx.x] = as2v[threadIdx.x]; sad[threadIdx.x] = ad2v[threadIdx.x]; }
    __syncthreads();

    int gid = blockIdx.x * 256 + threadIdx.x;   // GN*8 exact
    int node = gid >> 3, h = gid & 7;
    float adst = g_ad1[gid];
    float s = __expf(lrelu(g_as1[gid] + adst));     // self edge
    const float4* selfp = (const float4*)(g_h1 + (size_t)node * GHC + h * 8);
    float4 sv0 = selfp[0], sv1 = selfp[1];
    float4 a0 = make_float4(s * sv0.x, s * sv0.y, s * sv0.z, s * sv0.w);
    float4 a1 = make_float4(s * sv1.x, s * sv1.y, s * sv1.z, s * sv1.w);
    int beg = g_off[node], end = g_off[node + 1];
    for (int i = beg; i < end; i++) {
        int src = g_csr[i];
        float w = __expf(lrelu(__ldg(&g_as1[src * GH1 + h]) + adst));
        const float4* hp = (const float4*)(g_h1 + (size_t)src * GHC + h * 8);
        float4 v0 = __ldg(hp), v1 = __ldg(hp + 1);
        s += w;
        a0.x += w * v0.x; a0.y += w * v0.y; a0.z += w * v0.z; a0.w += w * v0.w;
        a1.x += w * v1.x; a1.y += w * v1.y; a1.z += w * v1.z; a1.w += w * v1.w;
    }
    float inv = 1.0f / (s + 1e-16f);
    float hp8[8] = {a0.x, a0.y, a0.z, a0.w, a1.x, a1.y, a1.z, a1.w};
    int base = node * GHC + h * 8;
#pragma unroll
    for (int c = 0; c < 8; c++) {
        float v = hp8[c] * inv + b1[h * 8 + c];
        hp8[c] = fmaxf(v, 0.f) * mask[base + c];
    }
    // partial z = hpost(rows h*8..h*8+7) @ W2
    float z[7] = {};
#pragma unroll
    for (int c = 0; c < 8; c++) {
        float hv = hp8[c];
        const float* wr = &sw[(h * 8 + c) * 7];
#pragma unroll
        for (int j = 0; j < 7; j++) z[j] += hv * wr[j];
    }
#pragma unroll
    for (int w = 1; w < 8; w <<= 1)
#pragma unroll
        for (int j = 0; j < 7; j++) z[j] += __shfl_xor_sync(0xffffffffu, z[j], w, 8);
    if (h == 0) {
        float as = 0.f, ad = 0.f;
        float* zp = g_z + (size_t)node * 8;
#pragma unroll
        for (int j = 0; j < 7; j++) {
            as += z[j] * sas[j];
            ad += z[j] * sad[j];
            zp[j] = z[j];
        }
        zp[7] = 0.f;
        g_as2[node] = as;
        g_ad2[node] = ad;
    }
}

// ---------------- layer-2 agg (8 lanes/node) + epilogue ----------------
__global__ __launch_bounds__(256) void k_agg2(const float* __restrict__ b2,
                                              float* __restrict__ out) {
    int gid = blockIdx.x * 256 + threadIdx.x;    // GN*8 exact
    int node = gid >> 3, c = gid & 7;
    float adst = g_ad2[node];
    float s = __expf(lrelu(g_as2[node] + adst));
    float acc = s * g_z[(size_t)node * 8 + c];
    int beg = g_off[node], end = g_off[node + 1];
    for (int i = beg; i < end; i++) {
        int src = g_csr[i];
        float w = __expf(lrelu(__ldg(&g_as2[src]) + adst));
        s += w;
        acc += w * __ldg(&g_z[(size_t)src * 8 + c]);
    }
    float xo = acc / (s + 1e-16f) + ((c < 7) ? b2[c] : 0.f);
    float xv = (c < 7) ? xo : -1e30f;
    float mx = xv;
#pragma unroll
    for (int w = 1; w < 8; w <<= 1) mx = fmaxf(mx, __shfl_xor_sync(0xffffffffu, mx, w, 8));
    float e = (c < 7) ? __expf(xo - mx) : 0.f;
    float sum = e;
#pragma unroll
    for (int w = 1; w < 8; w <<= 1) sum += __shfl_xor_sync(0xffffffffu, sum, w, 8);
    float lse = __logf(sum);
    float p = e / sum;
    if (c < 7) {
        out[(size_t)node * 7 + c] = xo - mx - lse;          // log_softmax
        out[700001 + (size_t)node * 7 + c] = p;             // softmax
    }
    // top2 over the 7 lanes (all lanes compute, lane 0 uses)
    float p1 = -1.f, p2 = -1.f;
#pragma unroll
    for (int j = 0; j < 7; j++) {
        float pj = __shfl_sync(0xffffffffu, p, j, 8);
        if (pj > p1) { p2 = p1; p1 = pj; }
        else if (pj > p2) { p2 = pj; }
    }
    float calib = (c == 0) ? (1.0f - p1 + p2) : 0.f;
    __shared__ float red[256];
    red[threadIdx.x] = calib;
    __syncthreads();
    for (int d = 128; d > 0; d >>= 1) {
        if (threadIdx.x < d) red[threadIdx.x] += red[threadIdx.x + d];
        __syncthreads();
    }
    if (threadIdx.x == 0) g_calib[blockIdx.x] = red[0];
}

__global__ void k_final(float* __restrict__ out) {
    __shared__ float sh[1024];
    float s = 0.f;
    for (int i = threadIdx.x; i < NB8; i += 1024) s += g_calib[i];
    sh[threadIdx.x] = s;
    __syncthreads();
    for (int d = 512; d > 0; d >>= 1) {
        if (threadIdx.x < d) sh[threadIdx.x] += sh[threadIdx.x + d];
        __syncthreads();
    }
    if (threadIdx.x == 0) out[700000] = sh[0] / (float)GN;
}

// ---------------- launch ----------------
extern "C" void kernel_launch(void* const* d_in, const int* in_sizes, int n_in,
                              void* d_out, int out_size) {
    const float* x        = (const float*)d_in[0];
    const int*   ei       = (const int*)d_in[1];
    const float* mask     = (const float*)d_in[2];
    const float* W1       = (const float*)d_in[3];
    const float* att_s1   = (const float*)d_in[4];
    const float* att_d1   = (const float*)d_in[5];
    const float* b1       = (const float*)d_in[6];
    const float* W2       = (const float*)d_in[7];
    const float* att_s2   = (const float*)d_in[8];
    const float* att_d2   = (const float*)d_in[9];
    const float* b2       = (const float*)d_in[10];
    float* out = (float*)d_out;

    cudaFuncSetAttribute(k_gemm1_tc, cudaFuncAttributeMaxDynamicSharedMemorySize, SMEM_SZ);

    const int TB = 256;
    int eg = (GE + TB - 1) / TB;

    // CSR build
    k_zero_deg<<<NCHUNK, TB>>>();
    k_hist<<<eg, TB>>>(ei);
    k_scan_block<<<NCHUNK, TB>>>();
    k_scan_part<<<1, 512>>>();
    k_scan_add<<<NCHUNK, TB>>>();
    k_scatter<<<eg, TB>>>(ei);

    // Layer 1 (+ fused alphas1)
    k_gemm1_tc<<<GM1_GRID, TB, SMEM_SZ>>>(x, W1, att_s1, att_d1);
    // agg1 + fused GEMM2 + alphas2
    k_agg1<<<NB8, TB>>>(b1, mask, W2, att_s2, att_d2);
    // agg2 + epilogue
    k_agg2<<<NB8, TB>>>(b2, out);
    k_final<<<1, 1024>>>(out);
}

// round 6
// speedup vs baseline: 1.7024x; 1.0754x over previous
#include <cuda_runtime.h>
#include <cuda_bf16.h>
#include <math.h>
#include <stdint.h>

#define GN 100000
#define GE 1600000
#define GF 500
#define GH1 8
#define GHC 64
#define GC2 7
#define NEG 0.2f
#define NCHUNK 391        // ceil(GN/256)
#define NB8 3125          // GN*8/256 exact
#define GM1_GRID 782      // ceil(GN/128)

// ---------------- scratch ----------------
__device__ int   g_deg[GN];
__device__ int   g_off[GN + 1];
__device__ int   g_cursor[GN];
__device__ int   g_csr[GE];
__device__ int   g_part[NCHUNK];
__device__ float g_h1[GN * GHC];
__device__ float g_as1[GN * GH1];
__device__ float g_ad1[GN * GH1];
__device__ float g_z[GN * 8];
__device__ float g_as2[GN];
__device__ float g_ad2[GN];
__device__ float g_calib[NB8];

__device__ __forceinline__ float lrelu(float v) { return v > 0.f ? v : NEG * v; }

// ---------------- CSR build ----------------
__global__ void k_zero_deg() {
    int i = blockIdx.x * blockDim.x + threadIdx.x;
    if (i < GN) g_deg[i] = 0;
}

__global__ void k_hist(const int* __restrict__ ei) {
    int e = blockIdx.x * blockDim.x + threadIdx.x;
    if (e < GE) atomicAdd(&g_deg[ei[GE + e]], 1);
}

__global__ void k_scan_block() {
    __shared__ int sh[256];
    int i = blockIdx.x * 256 + threadIdx.x;
    int v = (i < GN) ? g_deg[i] : 0;
    sh[threadIdx.x] = v;
    __syncthreads();
    for (int d = 1; d < 256; d <<= 1) {
        int t = (threadIdx.x >= d) ? sh[threadIdx.x - d] : 0;
        __syncthreads();
        sh[threadIdx.x] += t;
        __syncthreads();
    }
    if (i < GN) g_off[i] = sh[threadIdx.x] - v;
    if (threadIdx.x == 255) g_part[blockIdx.x] = sh[255];
}

__global__ void k_scan_part() {
    __shared__ int sh[512];
    int i = threadIdx.x;
    int v = (i < NCHUNK) ? g_part[i] : 0;
    sh[i] = v;
    __syncthreads();
    for (int d = 1; d < 512; d <<= 1) {
        int t = (i >= d) ? sh[i - d] : 0;
        __syncthreads();
        sh[i] += t;
        __syncthreads();
    }
    if (i < NCHUNK) g_part[i] = sh[i] - v;
    if (i == 511) g_off[GN] = sh[511];
}

__global__ void k_scan_add() {
    int i = blockIdx.x * 256 + threadIdx.x;
    if (i < GN) {
        int o = g_off[i] + g_part[blockIdx.x];
        g_off[i] = o;
        g_cursor[i] = o;
    }
}

__global__ void k_scatter(const int* __restrict__ ei) {
    int e = blockIdx.x * blockDim.x + threadIdx.x;
    if (e < GE) {
        int dst = ei[GE + e];
        int pos = atomicAdd(&g_cursor[dst], 1);
        g_csr[pos] = ei[e];
    }
}

// ---------------- GEMM1 via HMMA (split-bf16) + fused alphas1 ----------------
#define SA 72
#define SAW 36
#define OFF_AHI 0
#define OFF_ALO (128 * SA * 2)
#define OFF_BHI (2 * 128 * SA * 2)
#define OFF_BLO (2 * 128 * SA * 2 + 64 * SA * 2)
#define SMEM_SZ (2 * 128 * SA * 2 + 2 * 64 * SA * 2)

#define MMA_BF16(c, a, b) \
    asm volatile("mma.sync.aligned.m16n8k16.row.col.f32.bf16.bf16.f32 " \
        "{%0,%1,%2,%3}, {%4,%5,%6,%7}, {%8,%9}, {%0,%1,%2,%3};" \
        : "+f"((c)[0]), "+f"((c)[1]), "+f"((c)[2]), "+f"((c)[3]) \
        : "r"((a)[0]), "r"((a)[1]), "r"((a)[2]), "r"((a)[3]), "r"((b)[0]), "r"((b)[1]))

__global__ __launch_bounds__(256, 2) void k_gemm1_tc(const float* __restrict__ x,
                                                     const float* __restrict__ W,
                                                     const float* __restrict__ att_s,
                                                     const float* __restrict__ att_d) {
    extern __shared__ char smem[];
    uint32_t* A32h = (uint32_t*)(smem + OFF_AHI);
    uint32_t* A32l = (uint32_t*)(smem + OFF_ALO);
    uint32_t* B32h = (uint32_t*)(smem + OFF_BHI);
    uint32_t* B32l = (uint32_t*)(smem + OFF_BLO);

    int tid = threadIdx.x, wid = tid >> 5, lid = tid & 31;
    int wm = wid >> 1, wn = wid & 1;
    int g = lid >> 2, tg = lid & 3;
    int brow = blockIdx.x * 128;

    float acc[2][4][4] = {};

    for (int st = 0; st < 8; st++) {
        int k0 = st * 64;
        if (st) __syncthreads();
        for (int slot = tid; slot < 2048; slot += 256) {
            int r = slot >> 4, f4 = slot & 15;
            int row = brow + r, k = k0 + f4 * 4;
            float4 v = make_float4(0.f, 0.f, 0.f, 0.f);
            if (row < GN && k < GF) v = *(const float4*)(x + (size_t)row * GF + k);
            __nv_bfloat16 hx = __float2bfloat16(v.x), hy = __float2bfloat16(v.y);
            __nv_bfloat16 hz = __float2bfloat16(v.z), hw = __float2bfloat16(v.w);
            __nv_bfloat16 lx = __float2bfloat16(v.x - __bfloat162float(hx));
            __nv_bfloat16 ly = __float2bfloat16(v.y - __bfloat162float(hy));
            __nv_bfloat16 lz = __float2bfloat16(v.z - __bfloat162float(hz));
            __nv_bfloat16 lw = __float2bfloat16(v.w - __bfloat162float(hw));
            __nv_bfloat162 h01 = {hx, hy}, h23 = {hz, hw};
            __nv_bfloat162 l01 = {lx, ly}, l23 = {lz, lw};
            int w0 = r * SAW + f4 * 2;
            A32h[w0]     = *(uint32_t*)&h01;
            A32h[w0 + 1] = *(uint32_t*)&h23;
            A32l[w0]     = *(uint32_t*)&l01;
            A32l[w0 + 1] = *(uint32_t*)&l23;
        }
        for (int i = tid; i < 4096; i += 256) {
            int n = i & 63, kk = i >> 6;
            int k = k0 + kk;
            float w = (k < GF) ? W[(size_t)k * 64 + n] : 0.f;
            __nv_bfloat16 hw = __float2bfloat16(w);
            __nv_bfloat16 lw = __float2bfloat16(w - __bfloat162float(hw));
            *(__nv_bfloat16*)(smem + OFF_BHI + (n * SA + kk) * 2) = hw;
            *(__nv_bfloat16*)(smem + OFF_BLO + (n * SA + kk) * 2) = lw;
        }
        __syncthreads();

#pragma unroll
        for (int ks = 0; ks < 4; ks++) {
            int kw = ks * 8 + tg;
            uint32_t ah[2][4], al[2][4], bh[4][2], bl[4][2];
#pragma unroll
            for (int fm = 0; fm < 2; fm++) {
                int r0 = (wm * 32 + fm * 16 + g) * SAW;
                ah[fm][0] = A32h[r0 + kw];
                ah[fm][1] = A32h[r0 + 8 * SAW + kw];
                ah[fm][2] = A32h[r0 + kw + 4];
                ah[fm][3] = A32h[r0 + 8 * SAW + kw + 4];
                al[fm][0] = A32l[r0 + kw];
                al[fm][1] = A32l[r0 + 8 * SAW + kw];
                al[fm][2] = A32l[r0 + kw + 4];
                al[fm][3] = A32l[r0 + 8 * SAW + kw + 4];
            }
#pragma unroll
            for (int fn = 0; fn < 4; fn++) {
                int n0 = (wn * 32 + fn * 8 + g) * SAW;
                bh[fn][0] = B32h[n0 + kw];
                bh[fn][1] = B32h[n0 + kw + 4];
                bl[fn][0] = B32l[n0 + kw];
                bl[fn][1] = B32l[n0 + kw + 4];
            }
#pragma unroll
            for (int fm = 0; fm < 2; fm++)
#pragma unroll
                for (int fn = 0; fn < 4; fn++) {
                    MMA_BF16(acc[fm][fn], ah[fm], bh[fn]);
                    MMA_BF16(acc[fm][fn], ah[fm], bl[fn]);
                    MMA_BF16(acc[fm][fn], al[fm], bh[fn]);
                }
        }
    }

    // ---- epilogue: write h1 + fused as1/ad1
    float as_c[4][2], ad_c[4][2];
#pragma unroll
    for (int fn = 0; fn < 4; fn++) {
        int col = wn * 32 + fn * 8 + tg * 2;
        as_c[fn][0] = __ldg(&att_s[col]);     as_c[fn][1] = __ldg(&att_s[col + 1]);
        ad_c[fn][0] = __ldg(&att_d[col]);     ad_c[fn][1] = __ldg(&att_d[col + 1]);
    }
#pragma unroll
    for (int fm = 0; fm < 2; fm++) {
#pragma unroll
        for (int half = 0; half < 2; half++) {
            int row = brow + wm * 32 + fm * 16 + g + half * 8;
            float sh[4], dh[4];
#pragma unroll
            for (int fn = 0; fn < 4; fn++) {
                int col = wn * 32 + fn * 8 + tg * 2;
                float c0 = acc[fm][fn][2 * half], c1 = acc[fm][fn][2 * half + 1];
                if (row < GN)
                    *(float2*)&g_h1[(size_t)row * GHC + col] = make_float2(c0, c1);
                sh[fn] = c0 * as_c[fn][0] + c1 * as_c[fn][1];
                dh[fn] = c0 * ad_c[fn][0] + c1 * ad_c[fn][1];
            }
#pragma unroll
            for (int w = 1; w < 4; w <<= 1)
#pragma unroll
                for (int fn = 0; fn < 4; fn++) {
                    sh[fn] += __shfl_xor_sync(0xffffffffu, sh[fn], w, 4);
                    dh[fn] += __shfl_xor_sync(0xffffffffu, dh[fn], w, 4);
                }
            if (tg == 0 && row < GN) {
#pragma unroll
                for (int fn = 0; fn < 4; fn++) {
                    g_as1[row * 8 + wn * 4 + fn] = sh[fn];
                    g_ad1[row * 8 + wn * 4 + fn] = dh[fn];
                }
            }
        }
    }
}

// ---------------- layer-1 agg (no-max softmax) + fused GEMM2/alphas2 ----------------
__global__ __launch_bounds__(256) void k_agg1(const float* __restrict__ b1,
                                              const float* __restrict__ mask,
                                              const float* __restrict__ W2,
                                              const float* __restrict__ as2v,
                                              const float* __restrict__ ad2v) {
    __shared__ float sw[448], sas[7], sad[7];
    for (int i = threadIdx.x; i < 448; i += 256) sw[i] = W2[i];
    if (threadIdx.x < 7) { sas[threadIdx.x] = as2v[threadIdx.x]; sad[threadIdx.x] = ad2v[threadIdx.x]; }
    __syncthreads();

    int gid = blockIdx.x * 256 + threadIdx.x;   // GN*8 exact
    int node = gid >> 3, h = gid & 7;
    float adst = g_ad1[gid];
    float s = __expf(lrelu(g_as1[gid] + adst));     // self edge
    const float4* selfp = (const float4*)(g_h1 + (size_t)node * GHC + h * 8);
    float4 sv0 = selfp[0], sv1 = selfp[1];
    float4 a0 = make_float4(s * sv0.x, s * sv0.y, s * sv0.z, s * sv0.w);
    float4 a1 = make_float4(s * sv1.x, s * sv1.y, s * sv1.z, s * sv1.w);
    int beg = g_off[node], end = g_off[node + 1];
    for (int i = beg; i < end; i++) {
        int src = g_csr[i];
        float w = __expf(lrelu(__ldg(&g_as1[src * GH1 + h]) + adst));
        const float4* hp = (const float4*)(g_h1 + (size_t)src * GHC + h * 8);
        float4 v0 = __ldg(hp), v1 = __ldg(hp + 1);
        s += w;
        a0.x += w * v0.x; a0.y += w * v0.y; a0.z += w * v0.z; a0.w += w * v0.w;
        a1.x += w * v1.x; a1.y += w * v1.y; a1.z += w * v1.z; a1.w += w * v1.w;
    }
    float inv = 1.0f / (s + 1e-16f);
    float hp8[8] = {a0.x, a0.y, a0.z, a0.w, a1.x, a1.y, a1.z, a1.w};
    int base = node * GHC + h * 8;
#pragma unroll
    for (int c = 0; c < 8; c++) {
        float v = hp8[c] * inv + b1[h * 8 + c];
        hp8[c] = fmaxf(v, 0.f) * mask[base + c];
    }
    // partial z = hpost(rows h*8..h*8+7) @ W2
    float z[7] = {};
#pragma unroll
    for (int c = 0; c < 8; c++) {
        float hv = hp8[c];
        const float* wr = &sw[(h * 8 + c) * 7];
#pragma unroll
        for (int j = 0; j < 7; j++) z[j] += hv * wr[j];
    }
#pragma unroll
    for (int w = 1; w < 8; w <<= 1)
#pragma unroll
        for (int j = 0; j < 7; j++) z[j] += __shfl_xor_sync(0xffffffffu, z[j], w, 8);
    if (h == 0) {
        float as = 0.f, ad = 0.f;
        float* zp = g_z + (size_t)node * 8;
#pragma unroll
        for (int j = 0; j < 7; j++) {
            as += z[j] * sas[j];
            ad += z[j] * sad[j];
            zp[j] = z[j];
        }
        zp[7] = 0.f;
        g_as2[node] = as;
        g_ad2[node] = ad;
    }
}

// ---------------- layer-2 agg (8 lanes/node) + epilogue ----------------
__global__ __launch_bounds__(256) void k_agg2(const float* __restrict__ b2,
                                              float* __restrict__ out) {
    int gid = blockIdx.x * 256 + threadIdx.x;    // GN*8 exact
    int node = gid >> 3, c = gid & 7;
    float adst = g_ad2[node];
    float s = __expf(lrelu(g_as2[node] + adst));
    float acc = s * g_z[(size_t)node * 8 + c];
    int beg = g_off[node], end = g_off[node + 1];
    for (int i = beg; i < end; i++) {
        int src = g_csr[i];
        float w = __expf(lrelu(__ldg(&g_as2[src]) + adst));
        s += w;
        acc += w * __ldg(&g_z[(size_t)src * 8 + c]);
    }
    float xo = acc / (s + 1e-16f) + ((c < 7) ? b2[c] : 0.f);
    float xv = (c < 7) ? xo : -1e30f;
    float mx = xv;
#pragma unroll
    for (int w = 1; w < 8; w <<= 1) mx = fmaxf(mx, __shfl_xor_sync(0xffffffffu, mx, w, 8));
    float e = (c < 7) ? __expf(xo - mx) : 0.f;
    float sum = e;
#pragma unroll
    for (int w = 1; w < 8; w <<= 1) sum += __shfl_xor_sync(0xffffffffu, sum, w, 8);
    float lse = __logf(sum);
    float p = e / sum;
    if (c < 7) {
        out[(size_t)node * 7 + c] = xo - mx - lse;          // log_softmax
        out[700001 + (size_t)node * 7 + c] = p;             // softmax
    }
    float p1 = -1.f, p2 = -1.f;
#pragma unroll
    for (int j = 0; j < 7; j++) {
        float pj = __shfl_sync(0xffffffffu, p, j, 8);
        if (pj > p1) { p2 = p1; p1 = pj; }
        else if (pj > p2) { p2 = pj; }
    }
    float calib = (c == 0) ? (1.0f - p1 + p2) : 0.f;
    __shared__ float red[256];
    red[threadIdx.x] = calib;
    __syncthreads();
    for (int d = 128; d > 0; d >>= 1) {
        if (threadIdx.x < d) red[threadIdx.x] += red[threadIdx.x + d];
        __syncthreads();
    }
    if (threadIdx.x == 0) g_calib[blockIdx.x] = red[0];
}

__global__ void k_final(float* __restrict__ out) {
    __shared__ float sh[1024];
    float s = 0.f;
    for (int i = threadIdx.x; i < NB8; i += 1024) s += g_calib[i];
    sh[threadIdx.x] = s;
    __syncthreads();
    for (int d = 512; d > 0; d >>= 1) {
        if (threadIdx.x < d) sh[threadIdx.x] += sh[threadIdx.x + d];
        __syncthreads();
    }
    if (threadIdx.x == 0) out[700000] = sh[0] / (float)GN;
}

// ---------------- launch (fork-join: CSR on side stream || GEMM1 on main) ----------------
extern "C" void kernel_launch(void* const* d_in, const int* in_sizes, int n_in,
                              void* d_out, int out_size) {
    const float* x        = (const float*)d_in[0];
    const int*   ei       = (const int*)d_in[1];
    const float* mask     = (const float*)d_in[2];
    const float* W1       = (const float*)d_in[3];
    const float* att_s1   = (const float*)d_in[4];
    const float* att_d1   = (const float*)d_in[5];
    const float* b1       = (const float*)d_in[6];
    const float* W2       = (const float*)d_in[7];
    const float* att_s2   = (const float*)d_in[8];
    const float* att_d2   = (const float*)d_in[9];
    const float* b2       = (const float*)d_in[10];
    float* out = (float*)d_out;

    static cudaStream_t s2 = nullptr;
    static cudaEvent_t evFork = nullptr, evJoin = nullptr;
    if (s2 == nullptr) {
        cudaStreamCreateWithFlags(&s2, cudaStreamNonBlocking);
        cudaEventCreateWithFlags(&evFork, cudaEventDisableTiming);
        cudaEventCreateWithFlags(&evJoin, cudaEventDisableTiming);
        cudaFuncSetAttribute(k_gemm1_tc, cudaFuncAttributeMaxDynamicSharedMemorySize, SMEM_SZ);
    }

    const int TB = 256;
    int eg = (GE + TB - 1) / TB;

    // fork: CSR build on side stream
    cudaEventRecord(evFork, 0);
    cudaStreamWaitEvent(s2, evFork, 0);
    k_zero_deg<<<NCHUNK, TB, 0, s2>>>();
    k_hist<<<eg, TB, 0, s2>>>(ei);
    k_scan_block<<<NCHUNK, TB, 0, s2>>>();
    k_scan_part<<<1, 512, 0, s2>>>();
    k_scan_add<<<NCHUNK, TB, 0, s2>>>();
    k_scatter<<<eg, TB, 0, s2>>>(ei);
    cudaEventRecord(evJoin, s2);

    // concurrent: GEMM1 (+ fused alphas1) on main stream
    k_gemm1_tc<<<GM1_GRID, TB, SMEM_SZ>>>(x, W1, att_s1, att_d1);

    // join
    cudaStreamWaitEvent(0, evJoin, 0);

    // agg1 + fused GEMM2 + alphas2
    k_agg1<<<NB8, TB>>>(b1, mask, W2, att_s2, att_d2);
    // agg2 + epilogue
    k_agg2<<<NB8, TB>>>(b2, out);
    k_final<<<1, 1024>>>(out);
}

// round 7
// speedup vs baseline: 1.7058x; 1.0020x over previous
#include <cuda_runtime.h>
#include <cuda_bf16.h>
#include <math.h>
#include <stdint.h>

#define GN 100000
#define GE 1600000
#define GF 500
#define GH1 8
#define GHC 64
#define GC2 7
#define NEG 0.2f
#define NCHUNK 391        // ceil(GN/256)
#define NB8 3125          // GN*8/256 exact
#define GM1_GRID 782      // ceil(GN/128)

// ---------------- scratch ----------------
__device__ int   g_deg[GN];
__device__ int   g_off[GN + 1];
__device__ int   g_cursor[GN];
__device__ int   g_csr[GE];
__device__ int   g_part[NCHUNK];
__device__ float g_h1[GN * GHC];
__device__ float g_as1[GN * GH1];
__device__ float g_ad1[GN * GH1];
__device__ float g_z[GN * 8];
__device__ float g_as2[GN];
__device__ float g_ad2[GN];
__device__ float g_calib[NB8];

__device__ __forceinline__ float lrelu(float v) { return v > 0.f ? v : NEG * v; }

// FMA-only exp: avoids the MUFU pipe (rt_SMSP=8 -> 0.5/cyc/SM ceiling).
// n = rni(x*log2e) via magic-number add; 2^f degree-5 poly on [-0.5,0.5]; 2^n by exponent bits.
// Valid for |x| < ~80 (our inputs are |x| <~ 10). rel err ~1e-7.
__device__ __forceinline__ float fexp(float x) {
    const float LOG2E = 1.4426950408889634f;
    float t = fmaf(x, LOG2E, 12582912.0f);           // 1.5*2^23: forces round-to-nearest-int
    int   ni = __float_as_int(t) - 0x4B400000;       // integer n (unit-spaced region)
    float n = t - 12582912.0f;
    float f = fmaf(x, LOG2E, -n);                    // f in [-0.5, 0.5]
    float p = 0.0013333558f;
    p = fmaf(p, f, 0.0096181291f);
    p = fmaf(p, f, 0.0555041087f);
    p = fmaf(p, f, 0.2402265069f);
    p = fmaf(p, f, 0.6931471806f);
    p = fmaf(p, f, 1.0f);
    float r = __int_as_float((ni + 127) << 23);      // 2^n
    return p * r;
}

// ---------------- CSR build ----------------
__global__ void k_zero_deg() {
    int i = blockIdx.x * blockDim.x + threadIdx.x;
    if (i < GN) g_deg[i] = 0;
}

__global__ void k_hist(const int* __restrict__ ei) {
    int e = blockIdx.x * blockDim.x + threadIdx.x;
    if (e < GE) atomicAdd(&g_deg[ei[GE + e]], 1);
}

__global__ void k_scan_block() {
    __shared__ int sh[256];
    int i = blockIdx.x * 256 + threadIdx.x;
    int v = (i < GN) ? g_deg[i] : 0;
    sh[threadIdx.x] = v;
    __syncthreads();
    for (int d = 1; d < 256; d <<= 1) {
        int t = (threadIdx.x >= d) ? sh[threadIdx.x - d] : 0;
        __syncthreads();
        sh[threadIdx.x] += t;
        __syncthreads();
    }
    if (i < GN) g_off[i] = sh[threadIdx.x] - v;
    if (threadIdx.x == 255) g_part[blockIdx.x] = sh[255];
}

__global__ void k_scan_part() {
    __shared__ int sh[512];
    int i = threadIdx.x;
    int v = (i < NCHUNK) ? g_part[i] : 0;
    sh[i] = v;
    __syncthreads();
    for (int d = 1; d < 512; d <<= 1) {
        int t = (i >= d) ? sh[i - d] : 0;
        __syncthreads();
        sh[i] += t;
        __syncthreads();
    }
    if (i < NCHUNK) g_part[i] = sh[i] - v;
    if (i == 511) g_off[GN] = sh[511];
}

__global__ void k_scan_add() {
    int i = blockIdx.x * 256 + threadIdx.x;
    if (i < GN) {
        int o = g_off[i] + g_part[blockIdx.x];
        g_off[i] = o;
        g_cursor[i] = o;
    }
}

__global__ void k_scatter(const int* __restrict__ ei) {
    int e = blockIdx.x * blockDim.x + threadIdx.x;
    if (e < GE) {
        int dst = ei[GE + e];
        int pos = atomicAdd(&g_cursor[dst], 1);
        g_csr[pos] = ei[e];
    }
}

// ---------------- GEMM1 via HMMA (split-bf16) + fused alphas1 ----------------
#define SA 72
#define SAW 36
#define OFF_AHI 0
#define OFF_ALO (128 * SA * 2)
#define OFF_BHI (2 * 128 * SA * 2)
#define OFF_BLO (2 * 128 * SA * 2 + 64 * SA * 2)
#define SMEM_SZ (2 * 128 * SA * 2 + 2 * 64 * SA * 2)

#define MMA_BF16(c, a, b) \
    asm volatile("mma.sync.aligned.m16n8k16.row.col.f32.bf16.bf16.f32 " \
        "{%0,%1,%2,%3}, {%4,%5,%6,%7}, {%8,%9}, {%0,%1,%2,%3};" \
        : "+f"((c)[0]), "+f"((c)[1]), "+f"((c)[2]), "+f"((c)[3]) \
        : "r"((a)[0]), "r"((a)[1]), "r"((a)[2]), "r"((a)[3]), "r"((b)[0]), "r"((b)[1]))

__global__ __launch_bounds__(256, 2) void k_gemm1_tc(const float* __restrict__ x,
                                                     const float* __restrict__ W,
                                                     const float* __restrict__ att_s,
                                                     const float* __restrict__ att_d) {
    extern __shared__ char smem[];
    uint32_t* A32h = (uint32_t*)(smem + OFF_AHI);
    uint32_t* A32l = (uint32_t*)(smem + OFF_ALO);
    uint32_t* B32h = (uint32_t*)(smem + OFF_BHI);
    uint32_t* B32l = (uint32_t*)(smem + OFF_BLO);

    int tid = threadIdx.x, wid = tid >> 5, lid = tid & 31;
    int wm = wid >> 1, wn = wid & 1;
    int g = lid >> 2, tg = lid & 3;
    int brow = blockIdx.x * 128;

    float acc[2][4][4] = {};

    for (int st = 0; st < 8; st++) {
        int k0 = st * 64;
        if (st) __syncthreads();
        for (int slot = tid; slot < 2048; slot += 256) {
            int r = slot >> 4, f4 = slot & 15;
            int row = brow + r, k = k0 + f4 * 4;
            float4 v = make_float4(0.f, 0.f, 0.f, 0.f);
            if (row < GN && k < GF) v = *(const float4*)(x + (size_t)row * GF + k);
            __nv_bfloat16 hx = __float2bfloat16(v.x), hy = __float2bfloat16(v.y);
            __nv_bfloat16 hz = __float2bfloat16(v.z), hw = __float2bfloat16(v.w);
            __nv_bfloat16 lx = __float2bfloat16(v.x - __bfloat162float(hx));
            __nv_bfloat16 ly = __float2bfloat16(v.y - __bfloat162float(hy));
            __nv_bfloat16 lz = __float2bfloat16(v.z - __bfloat162float(hz));
            __nv_bfloat16 lw = __float2bfloat16(v.w - __bfloat162float(hw));
            __nv_bfloat162 h01 = {hx, hy}, h23 = {hz, hw};
            __nv_bfloat162 l01 = {lx, ly}, l23 = {lz, lw};
            int w0 = r * SAW + f4 * 2;
            A32h[w0]     = *(uint32_t*)&h01;
            A32h[w0 + 1] = *(uint32_t*)&h23;
            A32l[w0]     = *(uint32_t*)&l01;
            A32l[w0 + 1] = *(uint32_t*)&l23;
        }
        for (int i = tid; i < 4096; i += 256) {
            int n = i & 63, kk = i >> 6;
            int k = k0 + kk;
            float w = (k < GF) ? W[(size_t)k * 64 + n] : 0.f;
            __nv_bfloat16 hw = __float2bfloat16(w);
            __nv_bfloat16 lw = __float2bfloat16(w - __bfloat162float(hw));
            *(__nv_bfloat16*)(smem + OFF_BHI + (n * SA + kk) * 2) = hw;
            *(__nv_bfloat16*)(smem + OFF_BLO + (n * SA + kk) * 2) = lw;
        }
        __syncthreads();

#pragma unroll
        for (int ks = 0; ks < 4; ks++) {
            int kw = ks * 8 + tg;
            uint32_t ah[2][4], al[2][4], bh[4][2], bl[4][2];
#pragma unroll
            for (int fm = 0; fm < 2; fm++) {
                int r0 = (wm * 32 + fm * 16 + g) * SAW;
                ah[fm][0] = A32h[r0 + kw];
                ah[fm][1] = A32h[r0 + 8 * SAW + kw];
                ah[fm][2] = A32h[r0 + kw + 4];
                ah[fm][3] = A32h[r0 + 8 * SAW + kw + 4];
                al[fm][0] = A32l[r0 + kw];
                al[fm][1] = A32l[r0 + 8 * SAW + kw];
                al[fm][2] = A32l[r0 + kw + 4];
                al[fm][3] = A32l[r0 + 8 * SAW + kw + 4];
            }
#pragma unroll
            for (int fn = 0; fn < 4; fn++) {
                int n0 = (wn * 32 + fn * 8 + g) * SAW;
                bh[fn][0] = B32h[n0 + kw];
                bh[fn][1] = B32h[n0 + kw + 4];
                bl[fn][0] = B32l[n0 + kw];
                bl[fn][1] = B32l[n0 + kw + 4];
            }
#pragma unroll
            for (int fm = 0; fm < 2; fm++)
#pragma unroll
                for (int fn = 0; fn < 4; fn++) {
                    MMA_BF16(acc[fm][fn], ah[fm], bh[fn]);
                    MMA_BF16(acc[fm][fn], ah[fm], bl[fn]);
                    MMA_BF16(acc[fm][fn], al[fm], bh[fn]);
                }
        }
    }

    // ---- epilogue: write h1 + fused as1/ad1
    float as_c[4][2], ad_c[4][2];
#pragma unroll
    for (int fn = 0; fn < 4; fn++) {
        int col = wn * 32 + fn * 8 + tg * 2;
        as_c[fn][0] = __ldg(&att_s[col]);     as_c[fn][1] = __ldg(&att_s[col + 1]);
        ad_c[fn][0] = __ldg(&att_d[col]);     ad_c[fn][1] = __ldg(&att_d[col + 1]);
    }
#pragma unroll
    for (int fm = 0; fm < 2; fm++) {
#pragma unroll
        for (int half = 0; half < 2; half++) {
            int row = brow + wm * 32 + fm * 16 + g + half * 8;
            float sh[4], dh[4];
#pragma unroll
            for (int fn = 0; fn < 4; fn++) {
                int col = wn * 32 + fn * 8 + tg * 2;
                float c0 = acc[fm][fn][2 * half], c1 = acc[fm][fn][2 * half + 1];
                if (row < GN)
                    *(float2*)&g_h1[(size_t)row * GHC + col] = make_float2(c0, c1);
                sh[fn] = c0 * as_c[fn][0] + c1 * as_c[fn][1];
                dh[fn] = c0 * ad_c[fn][0] + c1 * ad_c[fn][1];
            }
#pragma unroll
            for (int w = 1; w < 4; w <<= 1)
#pragma unroll
                for (int fn = 0; fn < 4; fn++) {
                    sh[fn] += __shfl_xor_sync(0xffffffffu, sh[fn], w, 4);
                    dh[fn] += __shfl_xor_sync(0xffffffffu, dh[fn], w, 4);
                }
            if (tg == 0 && row < GN) {
#pragma unroll
                for (int fn = 0; fn < 4; fn++) {
                    g_as1[row * 8 + wn * 4 + fn] = sh[fn];
                    g_ad1[row * 8 + wn * 4 + fn] = dh[fn];
                }
            }
        }
    }
}

// ---------------- layer-1 agg (FMA-exp softmax) + fused GEMM2/alphas2 ----------------
__global__ __launch_bounds__(256) void k_agg1(const float* __restrict__ b1,
                                              const float* __restrict__ mask,
                                              const float* __restrict__ W2,
                                              const float* __restrict__ as2v,
                                              const float* __restrict__ ad2v) {
    __shared__ float sw[448], sas[7], sad[7];
    for (int i = threadIdx.x; i < 448; i += 256) sw[i] = W2[i];
    if (threadIdx.x < 7) { sas[threadIdx.x] = as2v[threadIdx.x]; sad[threadIdx.x] = ad2v[threadIdx.x]; }
    __syncthreads();

    int gid = blockIdx.x * 256 + threadIdx.x;   // GN*8 exact
    int node = gid >> 3, h = gid & 7;
    float adst = g_ad1[gid];
    float s = fexp(lrelu(g_as1[gid] + adst));     // self edge
    const float4* selfp = (const float4*)(g_h1 + (size_t)node * GHC + h * 8);
    float4 sv0 = selfp[0], sv1 = selfp[1];
    float4 a0 = make_float4(s * sv0.x, s * sv0.y, s * sv0.z, s * sv0.w);
    float4 a1 = make_float4(s * sv1.x, s * sv1.y, s * sv1.z, s * sv1.w);
    int beg = g_off[node], end = g_off[node + 1];
    for (int i = beg; i < end; i++) {
        int src = g_csr[i];
        float w = fexp(lrelu(__ldg(&g_as1[src * GH1 + h]) + adst));
        const float4* hp = (const float4*)(g_h1 + (size_t)src * GHC + h * 8);
        float4 v0 = __ldg(hp), v1 = __ldg(hp + 1);
        s += w;
        a0.x += w * v0.x; a0.y += w * v0.y; a0.z += w * v0.z; a0.w += w * v0.w;
        a1.x += w * v1.x; a1.y += w * v1.y; a1.z += w * v1.z; a1.w += w * v1.w;
    }
    float inv = 1.0f / (s + 1e-16f);
    float hp8[8] = {a0.x, a0.y, a0.z, a0.w, a1.x, a1.y, a1.z, a1.w};
    int base = node * GHC + h * 8;
#pragma unroll
    for (int c = 0; c < 8; c++) {
        float v = hp8[c] * inv + b1[h * 8 + c];
        hp8[c] = fmaxf(v, 0.f) * mask[base + c];
    }
    // partial z = hpost(rows h*8..h*8+7) @ W2
    float z[7] = {};
#pragma unroll
    for (int c = 0; c < 8; c++) {
        float hv = hp8[c];
        const float* wr = &sw[(h * 8 + c) * 7];
#pragma unroll
        for (int j = 0; j < 7; j++) z[j] += hv * wr[j];
    }
#pragma unroll
    for (int w = 1; w < 8; w <<= 1)
#pragma unroll
        for (int j = 0; j < 7; j++) z[j] += __shfl_xor_sync(0xffffffffu, z[j], w, 8);
    if (h == 0) {
        float as = 0.f, ad = 0.f;
        float* zp = g_z + (size_t)node * 8;
#pragma unroll
        for (int j = 0; j < 7; j++) {
            as += z[j] * sas[j];
            ad += z[j] * sad[j];
            zp[j] = z[j];
        }
        zp[7] = 0.f;
        g_as2[node] = as;
        g_ad2[node] = ad;
    }
}

// ---------------- layer-2 agg (8 lanes/node) + epilogue ----------------
__global__ __launch_bounds__(256) void k_agg2(const float* __restrict__ b2,
                                              float* __restrict__ out) {
    int gid = blockIdx.x * 256 + threadIdx.x;    // GN*8 exact
    int node = gid >> 3, c = gid & 7;
    float adst = g_ad2[node];
    float s = fexp(lrelu(g_as2[node] + adst));
    float acc = s * g_z[(size_t)node * 8 + c];
    int beg = g_off[node], end = g_off[node + 1];
    for (int i = beg; i < end; i++) {
        int src = g_csr[i];
        float w = fexp(lrelu(__ldg(&g_as2[src]) + adst));
        s += w;
        acc += w * __ldg(&g_z[(size_t)src * 8 + c]);
    }
    float xo = acc / (s + 1e-16f) + ((c < 7) ? b2[c] : 0.f);
    float xv = (c < 7) ? xo : -1e30f;
    float mx = xv;
#pragma unroll
    for (int w = 1; w < 8; w <<= 1) mx = fmaxf(mx, __shfl_xor_sync(0xffffffffu, mx, w, 8));
    float e = (c < 7) ? fexp(xo - mx) : 0.f;
    float sum = e;
#pragma unroll
    for (int w = 1; w < 8; w <<= 1) sum += __shfl_xor_sync(0xffffffffu, sum, w, 8);
    float lse = __logf(sum);
    float p = e / sum;
    if (c < 7) {
        out[(size_t)node * 7 + c] = xo - mx - lse;          // log_softmax
        out[700001 + (size_t)node * 7 + c] = p;             // softmax
    }
    float p1 = -1.f, p2 = -1.f;
#pragma unroll
    for (int j = 0; j < 7; j++) {
        float pj = __shfl_sync(0xffffffffu, p, j, 8);
        if (pj > p1) { p2 = p1; p1 = pj; }
        else if (pj > p2) { p2 = pj; }
    }
    float calib = (c == 0) ? (1.0f - p1 + p2) : 0.f;
    __shared__ float red[256];
    red[threadIdx.x] = calib;
    __syncthreads();
    for (int d = 128; d > 0; d >>= 1) {
        if (threadIdx.x < d) red[threadIdx.x] += red[threadIdx.x + d];
        __syncthreads();
    }
    if (threadIdx.x == 0) g_calib[blockIdx.x] = red[0];
}

__global__ void k_final(float* __restrict__ out) {
    __shared__ float sh[1024];
    float s = 0.f;
    for (int i = threadIdx.x; i < NB8; i += 1024) s += g_calib[i];
    sh[threadIdx.x] = s;
    __syncthreads();
    for (int d = 512; d > 0; d >>= 1) {
        if (threadIdx.x < d) sh[threadIdx.x] += sh[threadIdx.x + d];
        __syncthreads();
    }
    if (threadIdx.x == 0) out[700000] = sh[0] / (float)GN;
}

// ---------------- launch (fork-join: CSR on side stream || GEMM1 on main) ----------------
extern "C" void kernel_launch(void* const* d_in, const int* in_sizes, int n_in,
                              void* d_out, int out_size) {
    const float* x        = (const float*)d_in[0];
    const int*   ei       = (const int*)d_in[1];
    const float* mask     = (const float*)d_in[2];
    const float* W1       = (const float*)d_in[3];
    const float* att_s1   = (const float*)d_in[4];
    const float* att_d1   = (const float*)d_in[5];
    const float* b1       = (const float*)d_in[6];
    const float* W2       = (const float*)d_in[7];
    const float* att_s2   = (const float*)d_in[8];
    const float* att_d2   = (const float*)d_in[9];
    const float* b2       = (const float*)d_in[10];
    float* out = (float*)d_out;

    static cudaStream_t s2 = nullptr;
    static cudaEvent_t evFork = nullptr, evJoin = nullptr;
    if (s2 == nullptr) {
        cudaStreamCreateWithFlags(&s2, cudaStreamNonBlocking);
        cudaEventCreateWithFlags(&evFork, cudaEventDisableTiming);
        cudaEventCreateWithFlags(&evJoin, cudaEventDisableTiming);
        cudaFuncSetAttribute(k_gemm1_tc, cudaFuncAttributeMaxDynamicSharedMemorySize, SMEM_SZ);
    }

    const int TB = 256;
    int eg = (GE + TB - 1) / TB;

    // fork: CSR build on side stream
    cudaEventRecord(evFork, 0);
    cudaStreamWaitEvent(s2, evFork, 0);
    k_zero_deg<<<NCHUNK, TB, 0, s2>>>();
    k_hist<<<eg, TB, 0, s2>>>(ei);
    k_scan_block<<<NCHUNK, TB, 0, s2>>>();
    k_scan_part<<<1, 512, 0, s2>>>();
    k_scan_add<<<NCHUNK, TB, 0, s2>>>();
    k_scatter<<<eg, TB, 0, s2>>>(ei);
    cudaEventRecord(evJoin, s2);

    // concurrent: GEMM1 (+ fused alphas1) on main stream
    k_gemm1_tc<<<GM1_GRID, TB, SMEM_SZ>>>(x, W1, att_s1, att_d1);

    // join
    cudaStreamWaitEvent(0, evJoin, 0);

    // agg1 + fused GEMM2 + alphas2
    k_agg1<<<NB8, TB>>>(b1, mask, W2, att_s2, att_d2);
    // agg2 + epilogue
    k_agg2<<<NB8, TB>>>(b2, out);
    k_final<<<1, 1024>>>(out);
}